// round 2
// baseline (speedup 1.0000x reference)
#include <cuda_runtime.h>
#include <math.h>

// ---------------------------------------------------------------------------
// SwinTransformerBlock3D  — fp32 baseline
// GRID (16,64,64), B=2, C=96, H=6, hd=16, window 4x4x4 (N=64), shift (2,2,2)
// MLP 96->384->96, eps 1e-5
// ---------------------------------------------------------------------------

#define NI 16
#define NX 64
#define NT 64
#define LTOK (NI*NX*NT)        // 65536
#define BATCH 2
#define C 96
#define NH 6
#define HD 16
#define NW 64                  // tokens per window
#define NWIN_PER_B 1024        // 4*16*16
#define NBLK_A (BATCH*NWIN_PER_B)   // 2048
#define MLPH 384

// smem strides (padded to avoid 32-bank conflicts: stride % 32 != 0, odd for qkv)
#define XS 100                 // xbuf / obuf stride
#define QS 293                 // qkv stride (odd: 16*QS % 32 == 16 -> <=2-way)
#define SS 68                  // score stride
#define HS 388                 // hidden stride (mlp)

// intermediate y = x + attn_out   (scratch; device global, no allocation)
__device__ float g_ybuf[(size_t)BATCH * LTOK * C];

// ---------------------------------------------------------------------------
// Kernel A: LN1 + window gather + QKV + attention(+bias,softmax) + proj + residual
// one block per window, 256 threads
// ---------------------------------------------------------------------------
__global__ __launch_bounds__(256, 1)
void win_attn_kernel(const float* __restrict__ x,
                     const float* __restrict__ g1, const float* __restrict__ b1,
                     const float* __restrict__ qkv_w, const float* __restrict__ qkv_b,
                     const float* __restrict__ proj_w, const float* __restrict__ proj_b,
                     const float* __restrict__ bias_table)
{
    extern __shared__ float sm[];
    float* xbuf = sm;                       // [64][XS]  (reused as attention output)
    float* qkv  = sm + NW * XS;             // [64][QS]
    float* sbuf = qkv + NW * QS;            // [64][SS]
    unsigned short* rel = (unsigned short*)(sbuf + NW * SS);  // [4096]
    int* srcidx = (int*)(rel + 4096);       // [64]

    const int tid = threadIdx.x;
    const int wb  = blockIdx.x;
    const int bb  = wb >> 10;               // batch
    const int w   = wb & 1023;
    const int iw  = w >> 8;
    const int xw  = (w >> 4) & 15;
    const int tw  = w & 15;

    // -------- precompute source token indices (roll -2 then partition) + rel idx
    if (tid < NW) {
        int i  = tid >> 4, xx = (tid >> 2) & 3, tt = tid & 3;
        int gi = (iw * 4 + i  + 2) & 15;
        int gx = (xw * 4 + xx + 2) & 63;
        int gt = (tw * 4 + tt + 2) & 63;
        srcidx[tid] = ((gi << 6) + gx) * 64 + gt;
    }
    for (int p = tid; p < NW * NW; p += 256) {
        int n = p >> 6, m = p & 63;
        int di = (n >> 4)        - (m >> 4)        + 3;
        int dx = ((n >> 2) & 3)  - ((m >> 2) & 3)  + 3;
        int dt = (n & 3)         - (m & 3)         + 3;
        rel[p] = (unsigned short)((di * 7 + dx) * 7 + dt);
    }
    __syncthreads();

    // -------- LN1: 4 lanes per token, values kept in registers
    {
        const int n = tid >> 2, q = tid & 3;
        const float* xr = x + ((size_t)(bb * LTOK + srcidx[n])) * C;
        float v[24];
        float s = 0.f, ss = 0.f;
        #pragma unroll
        for (int j = 0; j < 24; j++) {
            float t = xr[q * 24 + j];
            v[j] = t; s += t; ss += t * t;
        }
        s  += __shfl_xor_sync(0xffffffffu, s, 1);
        ss += __shfl_xor_sync(0xffffffffu, ss, 1);
        s  += __shfl_xor_sync(0xffffffffu, s, 2);
        ss += __shfl_xor_sync(0xffffffffu, ss, 2);
        float mean = s * (1.f / 96.f);
        float var  = ss * (1.f / 96.f) - mean * mean;
        float rstd = rsqrtf(var + 1e-5f);
        #pragma unroll
        for (int j = 0; j < 24; j++) {
            int c = q * 24 + j;
            xbuf[n * XS + c] = (v[j] - mean) * rstd * g1[c] + b1[c];
        }
    }
    __syncthreads();

    // -------- QKV GEMM: [64 x 96] @ [96 x 288], 8 rows x 9 cols per thread
    {
        const int rg = tid >> 5;           // 8 row groups of 8
        const int lane = tid & 31;         // cols lane + 32*j
        float acc[8][9];
        #pragma unroll
        for (int j = 0; j < 9; j++) {
            float bj = qkv_b[lane + 32 * j];
            #pragma unroll
            for (int r = 0; r < 8; r++) acc[r][j] = bj;
        }
        for (int k = 0; k < C; k++) {
            float a[8];
            #pragma unroll
            for (int r = 0; r < 8; r++) a[r] = xbuf[(rg * 8 + r) * XS + k];
            #pragma unroll
            for (int j = 0; j < 9; j++) {
                float wv = __ldg(&qkv_w[k * 288 + lane + 32 * j]);
                #pragma unroll
                for (int r = 0; r < 8; r++) acc[r][j] += a[r] * wv;
            }
        }
        #pragma unroll
        for (int r = 0; r < 8; r++)
            #pragma unroll
            for (int j = 0; j < 9; j++)
                qkv[(rg * 8 + r) * QS + lane + 32 * j] = acc[r][j];
    }
    __syncthreads();

    // -------- attention, head loop.  row n = tid/4, quarter q = tid&3
    {
        const int an = tid >> 2, aq = tid & 3;
        const float scale = 0.25f;   // hd^-0.5

        for (int h = 0; h < NH; h++) {
            // load q row into regs
            float qr[HD];
            #pragma unroll
            for (int d = 0; d < HD; d++) qr[d] = qkv[an * QS + h * HD + d];

            // scores for 16 columns
            float p[16];
            #pragma unroll
            for (int mm = 0; mm < 16; mm++) {
                int m = aq * 16 + mm;
                float d = 0.f;
                #pragma unroll
                for (int dd = 0; dd < HD; dd++)
                    d += qr[dd] * qkv[m * QS + C + h * HD + dd];
                int rdx = rel[an * 64 + m];
                p[mm] = d * scale + __ldg(&bias_table[rdx * NH + h]);
            }
            // softmax across the 4 lanes of this row
            float mx = -1e30f;
            #pragma unroll
            for (int mm = 0; mm < 16; mm++) mx = fmaxf(mx, p[mm]);
            mx = fmaxf(mx, __shfl_xor_sync(0xffffffffu, mx, 1));
            mx = fmaxf(mx, __shfl_xor_sync(0xffffffffu, mx, 2));
            float sum = 0.f;
            #pragma unroll
            for (int mm = 0; mm < 16; mm++) { p[mm] = __expf(p[mm] - mx); sum += p[mm]; }
            sum += __shfl_xor_sync(0xffffffffu, sum, 1);
            sum += __shfl_xor_sync(0xffffffffu, sum, 2);
            float inv = 1.f / sum;
            #pragma unroll
            for (int mm = 0; mm < 16; mm++)
                sbuf[an * SS + aq * 16 + mm] = p[mm] * inv;
            __syncwarp();

            // o[n][d] for d = aq*4 .. aq*4+3
            float o0 = 0.f, o1 = 0.f, o2 = 0.f, o3 = 0.f;
            const float* vb = qkv + 2 * C + h * HD + aq * 4;
            for (int m = 0; m < NW; m++) {
                float pm = sbuf[an * SS + m];
                const float* vr = vb + m * QS;
                o0 += pm * vr[0]; o1 += pm * vr[1];
                o2 += pm * vr[2]; o3 += pm * vr[3];
            }
            float* ob = xbuf + an * XS + h * HD + aq * 4;   // xbuf reused as obuf
            ob[0] = o0; ob[1] = o1; ob[2] = o2; ob[3] = o3;
            __syncwarp();
        }
    }
    __syncthreads();

    // -------- proj GEMM [64x96]@[96x96] + residual + scatter to y
    {
        const int rg = tid >> 5;
        const int lane = tid & 31;
        float acc[8][3];
        #pragma unroll
        for (int j = 0; j < 3; j++) {
            float bj = proj_b[lane + 32 * j];
            #pragma unroll
            for (int r = 0; r < 8; r++) acc[r][j] = bj;
        }
        for (int k = 0; k < C; k++) {
            float a[8];
            #pragma unroll
            for (int r = 0; r < 8; r++) a[r] = xbuf[(rg * 8 + r) * XS + k];
            #pragma unroll
            for (int j = 0; j < 3; j++) {
                float wv = __ldg(&proj_w[k * C + lane + 32 * j]);
                #pragma unroll
                for (int r = 0; r < 8; r++) acc[r][j] += a[r] * wv;
            }
        }
        #pragma unroll
        for (int r = 0; r < 8; r++) {
            size_t base = ((size_t)(bb * LTOK + srcidx[rg * 8 + r])) * C;
            const float* xr = x + base;
            float* yw = g_ybuf + base;
            #pragma unroll
            for (int j = 0; j < 3; j++) {
                int c = lane + 32 * j;
                yw[c] = xr[c] + acc[r][j];
            }
        }
    }
}

// ---------------------------------------------------------------------------
// Kernel B: LN2 + MLP (96->384 GELU -> 96) + residual
// one block per 64 contiguous tokens
// ---------------------------------------------------------------------------
__global__ __launch_bounds__(256, 1)
void mlp_kernel(const float* __restrict__ g2, const float* __restrict__ b2,
                const float* __restrict__ w1, const float* __restrict__ bb1,
                const float* __restrict__ w2, const float* __restrict__ bb2,
                float* __restrict__ out)
{
    extern __shared__ float sm[];
    float* h2  = sm;                 // [64][XS]
    float* hid = sm + NW * XS;       // [64][HS]

    const int tid = threadIdx.x;
    const int t0 = blockIdx.x * NW;

    // LN2
    {
        const int n = tid >> 2, q = tid & 3;
        const float* yr = g_ybuf + (size_t)(t0 + n) * C;
        float v[24];
        float s = 0.f, ss = 0.f;
        #pragma unroll
        for (int j = 0; j < 24; j++) {
            float t = yr[q * 24 + j];
            v[j] = t; s += t; ss += t * t;
        }
        s  += __shfl_xor_sync(0xffffffffu, s, 1);
        ss += __shfl_xor_sync(0xffffffffu, ss, 1);
        s  += __shfl_xor_sync(0xffffffffu, s, 2);
        ss += __shfl_xor_sync(0xffffffffu, ss, 2);
        float mean = s * (1.f / 96.f);
        float var  = ss * (1.f / 96.f) - mean * mean;
        float rstd = rsqrtf(var + 1e-5f);
        #pragma unroll
        for (int j = 0; j < 24; j++) {
            int c = q * 24 + j;
            h2[n * XS + c] = (v[j] - mean) * rstd * g2[c] + b2[c];
        }
    }
    __syncthreads();

    // GEMM1: [64x96]@[96x384] + bias + exact GELU  (8 rows x 12 cols / thread)
    {
        const int rg = tid >> 5;
        const int lane = tid & 31;
        float acc[8][12];
        #pragma unroll
        for (int j = 0; j < 12; j++) {
            float bj = bb1[lane + 32 * j];
            #pragma unroll
            for (int r = 0; r < 8; r++) acc[r][j] = bj;
        }
        for (int k = 0; k < C; k++) {
            float a[8];
            #pragma unroll
            for (int r = 0; r < 8; r++) a[r] = h2[(rg * 8 + r) * XS + k];
            #pragma unroll
            for (int j = 0; j < 12; j++) {
                float wv = __ldg(&w1[k * MLPH + lane + 32 * j]);
                #pragma unroll
                for (int r = 0; r < 8; r++) acc[r][j] += a[r] * wv;
            }
        }
        #pragma unroll
        for (int r = 0; r < 8; r++)
            #pragma unroll
            for (int j = 0; j < 12; j++) {
                float u = acc[r][j];
                float g = 0.5f * u * (1.0f + erff(u * 0.70710678118654752f));
                hid[(rg * 8 + r) * HS + lane + 32 * j] = g;
            }
    }
    __syncthreads();

    // GEMM2: [64x384]@[384x96] + bias + residual, write out
    {
        const int rg = tid >> 5;
        const int lane = tid & 31;
        float acc[8][3];
        #pragma unroll
        for (int j = 0; j < 3; j++) {
            float bj = bb2[lane + 32 * j];
            #pragma unroll
            for (int r = 0; r < 8; r++) acc[r][j] = bj;
        }
        for (int k = 0; k < MLPH; k++) {
            float a[8];
            #pragma unroll
            for (int r = 0; r < 8; r++) a[r] = hid[(rg * 8 + r) * HS + k];
            #pragma unroll
            for (int j = 0; j < 3; j++) {
                float wv = __ldg(&w2[k * C + lane + 32 * j]);
                #pragma unroll
                for (int r = 0; r < 8; r++) acc[r][j] += a[r] * wv;
            }
        }
        #pragma unroll
        for (int r = 0; r < 8; r++) {
            size_t base = (size_t)(t0 + rg * 8 + r) * C;
            const float* yr = g_ybuf + base;
            float* ow = out + base;
            #pragma unroll
            for (int j = 0; j < 3; j++) {
                int c = lane + 32 * j;
                ow[c] = yr[c] + acc[r][j];
            }
        }
    }
}

// ---------------------------------------------------------------------------
extern "C" void kernel_launch(void* const* d_in, const int* in_sizes, int n_in,
                              void* d_out, int out_size)
{
    const float* x        = (const float*)d_in[0];
    const float* norm1_g  = (const float*)d_in[1];
    const float* norm1_b  = (const float*)d_in[2];
    const float* qkv_w    = (const float*)d_in[3];
    const float* qkv_b    = (const float*)d_in[4];
    const float* proj_w   = (const float*)d_in[5];
    const float* proj_b   = (const float*)d_in[6];
    const float* bias_tab = (const float*)d_in[7];
    const float* norm2_g  = (const float*)d_in[8];
    const float* norm2_b  = (const float*)d_in[9];
    const float* mlp_w1   = (const float*)d_in[10];
    const float* mlp_b1   = (const float*)d_in[11];
    const float* mlp_w2   = (const float*)d_in[12];
    const float* mlp_b2   = (const float*)d_in[13];
    float* out = (float*)d_out;

    const int SMEM_A = (NW * XS + NW * QS + NW * SS) * 4 + 4096 * 2 + NW * 4;
    const int SMEM_B = (NW * XS + NW * HS) * 4;

    cudaFuncSetAttribute(win_attn_kernel,
                         cudaFuncAttributeMaxDynamicSharedMemorySize, SMEM_A);
    cudaFuncSetAttribute(mlp_kernel,
                         cudaFuncAttributeMaxDynamicSharedMemorySize, SMEM_B);

    win_attn_kernel<<<NBLK_A, 256, SMEM_A>>>(x, norm1_g, norm1_b,
                                             qkv_w, qkv_b, proj_w, proj_b,
                                             bias_tab);
    mlp_kernel<<<(BATCH * LTOK) / NW, 256, SMEM_B>>>(norm2_g, norm2_b,
                                                     mlp_w1, mlp_b1,
                                                     mlp_w2, mlp_b2, out);
}

// round 3
// speedup vs baseline: 1.1713x; 1.1713x over previous
#include <cuda_runtime.h>
#include <math.h>

// ---------------------------------------------------------------------------
// SwinTransformerBlock3D — fp32 with packed f32x2 FMA (sm_103a)
// GRID (16,64,64), B=2, C=96, H=6, hd=16, window 4x4x4 (N=64), shift (2,2,2)
// ---------------------------------------------------------------------------

#define LTOK (16*64*64)        // 65536 tokens per batch
#define BATCH 2
#define C 96
#define NH 6
#define HD 16
#define NW 64
#define NBLK_A 2048
#define MLPH 384

typedef unsigned long long u64t;

// scratch: y = x + attn_out
__device__ float g_ybuf[(size_t)BATCH * LTOK * C];

// ---------------- f32x2 / shared-memory helpers ----------------------------
__device__ __forceinline__ unsigned sp(const void* p) {
    return (unsigned)__cvta_generic_to_shared(p);
}
__device__ __forceinline__ u64t ldsb64(const float* p) {
    u64t v; asm volatile("ld.shared.b64 %0,[%1];" : "=l"(v) : "r"(sp(p))); return v;
}
__device__ __forceinline__ void ldsv2b64(u64t& a, u64t& b, const float* p) {
    asm volatile("ld.shared.v2.b64 {%0,%1},[%2];" : "=l"(a), "=l"(b) : "r"(sp(p)));
}
__device__ __forceinline__ float2 ldsf2(const float* p) {
    float2 r; asm volatile("ld.shared.v2.f32 {%0,%1},[%2];"
                           : "=f"(r.x), "=f"(r.y) : "r"(sp(p))); return r;
}
__device__ __forceinline__ float4 ldsf4(const float* p) {
    float4 r; asm volatile("ld.shared.v4.f32 {%0,%1,%2,%3},[%4];"
                           : "=f"(r.x),"=f"(r.y),"=f"(r.z),"=f"(r.w) : "r"(sp(p))); return r;
}
__device__ __forceinline__ void stsb64(float* p, u64t v) {
    asm volatile("st.shared.b64 [%0],%1;" :: "r"(sp(p)), "l"(v));
}
__device__ __forceinline__ u64t pk2(float x, float y) {
    u64t r; asm("mov.b64 %0,{%1,%2};" : "=l"(r) : "f"(x), "f"(y)); return r;
}
__device__ __forceinline__ u64t dup2(float x) { return pk2(x, x); }
__device__ __forceinline__ float2 up2(u64t v) {
    float2 r; asm("mov.b64 {%0,%1},%2;" : "=f"(r.x), "=f"(r.y) : "l"(v)); return r;
}
__device__ __forceinline__ void fma2(u64t& d, u64t a, u64t b) {
    asm("fma.rn.f32x2 %0,%1,%2,%0;" : "+l"(d) : "l"(a), "l"(b));
}

// smem float offsets, kernel A
#define A_XT    0        // [96][68]  LN1 out transposed; reused as oT
#define A_Q     6528     // [64][100]
#define A_KT    12928    // [96][68]  kT[c][m]
#define A_V     19456    // [64][100]
#define A_S     25856    // [64][68]  probs
#define A_BIAS  30208    // [2058]
#define A_REL   32268    // u16[4096]
#define A_SRC   34316    // int[64]
#define A_TOT   34380

// ---------------------------------------------------------------------------
// Kernel A: LN1 + gather + QKV + attention + proj + residual -> g_ybuf
// ---------------------------------------------------------------------------
__global__ __launch_bounds__(512, 1)
void win_attn_kernel(const float* __restrict__ x,
                     const float* __restrict__ g1, const float* __restrict__ b1,
                     const float* __restrict__ qkv_w, const float* __restrict__ qkv_b,
                     const float* __restrict__ proj_w, const float* __restrict__ proj_b,
                     const float* __restrict__ bias_table)
{
    extern __shared__ float smf[];
    float* xT   = smf + A_XT;
    float* qbuf = smf + A_Q;
    float* kT   = smf + A_KT;
    float* vbuf = smf + A_V;
    float* sbuf = smf + A_S;
    float* sbias = smf + A_BIAS;
    unsigned short* rel = (unsigned short*)(smf + A_REL);
    int* srcidx = (int*)(smf + A_SRC);

    const int tid = threadIdx.x;
    const int wb = blockIdx.x;
    const int bb = wb >> 10;
    const int w  = wb & 1023;
    const int iw = w >> 8, xw = (w >> 4) & 15, tw = w & 15;

    if (tid < NW) {
        int i = tid >> 4, xx = (tid >> 2) & 3, tt = tid & 3;
        int gi = (iw * 4 + i  + 2) & 15;
        int gx = (xw * 4 + xx + 2) & 63;
        int gt = (tw * 4 + tt + 2) & 63;
        srcidx[tid] = ((gi << 6) + gx) * 64 + gt;
    }
    for (int p = tid; p < 4096; p += 512) {
        int n = p >> 6, m = p & 63;
        int di = (n >> 4)       - (m >> 4)       + 3;
        int dx = ((n >> 2) & 3) - ((m >> 2) & 3) + 3;
        int dt = (n & 3)        - (m & 3)        + 3;
        rel[p] = (unsigned short)((di * 7 + dx) * 7 + dt);
    }
    for (int i = tid; i < 343 * NH; i += 512) sbias[i] = bias_table[i];
    __syncthreads();

    // ---- LN1 (8 lanes per token, 12 ch each), write transposed xT[c][n]
    {
        const int n = tid >> 3, q8 = tid & 7;
        const float* xr = x + ((size_t)(bb * LTOK + srcidx[n])) * C + q8 * 12;
        float v[12]; float s = 0.f, ss = 0.f;
        #pragma unroll
        for (int j = 0; j < 12; j++) { float t = xr[j]; v[j] = t; s += t; ss += t * t; }
        s  += __shfl_xor_sync(0xffffffffu, s, 1);  ss += __shfl_xor_sync(0xffffffffu, ss, 1);
        s  += __shfl_xor_sync(0xffffffffu, s, 2);  ss += __shfl_xor_sync(0xffffffffu, ss, 2);
        s  += __shfl_xor_sync(0xffffffffu, s, 4);  ss += __shfl_xor_sync(0xffffffffu, ss, 4);
        float mean = s * (1.f / 96.f);
        float var  = ss * (1.f / 96.f) - mean * mean;
        float rstd = rsqrtf(var + 1e-5f);
        #pragma unroll
        for (int j = 0; j < 12; j++) {
            int c = q8 * 12 + j;
            xT[c * 68 + n] = (v[j] - mean) * rstd * g1[c] + b1[c];
        }
    }
    __syncthreads();

    // ---- QKV GEMM [64x96]@[96x288]: 16 rowgroups x 4 rows, 9 cols/thread
    {
        const int rg = tid >> 5, lane = tid & 31;
        const int r0 = rg * 4;
        u64t acc[2][9];
        #pragma unroll
        for (int j = 0; j < 9; j++) {
            u64t bj = dup2(qkv_b[lane + 32 * j]);
            acc[0][j] = bj; acc[1][j] = bj;
        }
        #pragma unroll 2
        for (int k = 0; k < C; k++) {
            u64t a0 = ldsb64(xT + k * 68 + r0);
            u64t a1 = ldsb64(xT + k * 68 + r0 + 2);
            const float* wr = qkv_w + k * 288 + lane;
            #pragma unroll
            for (int j = 0; j < 9; j++) {
                u64t wd = dup2(__ldg(wr + 32 * j));
                fma2(acc[0][j], a0, wd);
                fma2(acc[1][j], a1, wd);
            }
        }
        #pragma unroll
        for (int p = 0; p < 2; p++) {
            int row = r0 + 2 * p;
            #pragma unroll
            for (int j = 0; j < 9; j++) {
                int c = lane + 32 * j;
                if (j < 3) {
                    float2 t = up2(acc[p][j]);
                    qbuf[row * 100 + c] = t.x; qbuf[(row + 1) * 100 + c] = t.y;
                } else if (j < 6) {
                    stsb64(kT + (c - 96) * 68 + row, acc[p][j]);   // pairs = rows
                } else {
                    float2 t = up2(acc[p][j]);
                    vbuf[row * 100 + (c - 192)] = t.x;
                    vbuf[(row + 1) * 100 + (c - 192)] = t.y;
                }
            }
        }
    }
    __syncthreads();

    float* oT = xT;   // reuse LN1 buffer for attention output (transposed)

    // ---- attention: row n = tid>>3, sub = tid&7 -> cols m0..m0+7, dims sub*2..+1
    {
        const int n = tid >> 3, sub = tid & 7;
        const int m0 = sub * 8;
        #pragma unroll 1
        for (int h = 0; h < NH; h++) {
            const int hb = h * HD;
            u64t qd[HD];
            #pragma unroll
            for (int dd = 0; dd < HD; dd++) qd[dd] = dup2(qbuf[n * 100 + hb + dd]);

            u64t p2[4] = {0ull, 0ull, 0ull, 0ull};
            #pragma unroll
            for (int dd = 0; dd < HD; dd++) {
                const float* kp = kT + (hb + dd) * 68 + m0;
                u64t k01, k23, k45, k67;
                ldsv2b64(k01, k23, kp);
                ldsv2b64(k45, k67, kp + 4);
                fma2(p2[0], qd[dd], k01); fma2(p2[1], qd[dd], k23);
                fma2(p2[2], qd[dd], k45); fma2(p2[3], qd[dd], k67);
            }
            float p[8];
            #pragma unroll
            for (int i = 0; i < 4; i++) { float2 t = up2(p2[i]); p[2*i] = t.x; p[2*i+1] = t.y; }
            #pragma unroll
            for (int i = 0; i < 8; i++) {
                int rdx = rel[n * 64 + m0 + i];
                p[i] = p[i] * 0.25f + sbias[rdx * NH + h];
            }
            float mx = -1e30f;
            #pragma unroll
            for (int i = 0; i < 8; i++) mx = fmaxf(mx, p[i]);
            mx = fmaxf(mx, __shfl_xor_sync(0xffffffffu, mx, 1));
            mx = fmaxf(mx, __shfl_xor_sync(0xffffffffu, mx, 2));
            mx = fmaxf(mx, __shfl_xor_sync(0xffffffffu, mx, 4));
            float sum = 0.f;
            #pragma unroll
            for (int i = 0; i < 8; i++) { p[i] = __expf(p[i] - mx); sum += p[i]; }
            sum += __shfl_xor_sync(0xffffffffu, sum, 1);
            sum += __shfl_xor_sync(0xffffffffu, sum, 2);
            sum += __shfl_xor_sync(0xffffffffu, sum, 4);
            float inv = 1.f / sum;
            #pragma unroll
            for (int i = 0; i < 8; i++) sbuf[n * 68 + m0 + i] = p[i] * inv;
            __syncwarp();

            // AV: o[d0], o[d0+1], d0 = sub*2
            float o0 = 0.f, o1 = 0.f, o0b = 0.f, o1b = 0.f;
            const float* vb = vbuf + hb + sub * 2;
            #pragma unroll
            for (int m4 = 0; m4 < 16; m4++) {
                float4 pr = ldsf4(sbuf + n * 68 + m4 * 4);
                const float* vm = vb + (m4 * 4) * 100;
                float2 v0 = ldsf2(vm);         o0  += pr.x * v0.x; o1  += pr.x * v0.y;
                float2 v1 = ldsf2(vm + 100);   o0b += pr.y * v1.x; o1b += pr.y * v1.y;
                float2 v2 = ldsf2(vm + 200);   o0  += pr.z * v2.x; o1  += pr.z * v2.y;
                float2 v3 = ldsf2(vm + 300);   o0b += pr.w * v3.x; o1b += pr.w * v3.y;
            }
            oT[(hb + sub * 2) * 68 + n]     = o0 + o0b;
            oT[(hb + sub * 2 + 1) * 68 + n] = o1 + o1b;
            __syncwarp();
        }
    }
    __syncthreads();

    // ---- proj [64x96]@[96x96] + residual -> g_ybuf
    {
        const int rg = tid >> 5, lane = tid & 31;
        const int r0 = rg * 4;
        u64t acc[2][3];
        #pragma unroll
        for (int j = 0; j < 3; j++) {
            u64t bj = dup2(proj_b[lane + 32 * j]);
            acc[0][j] = bj; acc[1][j] = bj;
        }
        #pragma unroll 2
        for (int k = 0; k < C; k++) {
            u64t a0 = ldsb64(oT + k * 68 + r0);
            u64t a1 = ldsb64(oT + k * 68 + r0 + 2);
            const float* wr = proj_w + k * C + lane;
            #pragma unroll
            for (int j = 0; j < 3; j++) {
                u64t wd = dup2(__ldg(wr + 32 * j));
                fma2(acc[0][j], a0, wd);
                fma2(acc[1][j], a1, wd);
            }
        }
        #pragma unroll
        for (int p = 0; p < 2; p++) {
            int row = r0 + 2 * p;
            size_t ba = ((size_t)(bb * LTOK + srcidx[row])) * C;
            size_t bbs = ((size_t)(bb * LTOK + srcidx[row + 1])) * C;
            #pragma unroll
            for (int j = 0; j < 3; j++) {
                int c = lane + 32 * j;
                float2 t = up2(acc[p][j]);
                g_ybuf[ba + c]  = x[ba + c]  + t.x;
                g_ybuf[bbs + c] = x[bbs + c] + t.y;
            }
        }
    }
}

// ---------------------------------------------------------------------------
// Kernel B: LN2 + MLP (96->384 GELU ->96, split-K on GEMM2) + residual
// ---------------------------------------------------------------------------
#define B_H2T  0        // [96][68], reused as reduction buffer [64][100]
#define B_HID  6528     // [384][68]
#define B_TOT  32640

__global__ __launch_bounds__(512, 1)
void mlp_kernel(const float* __restrict__ g2, const float* __restrict__ b2,
                const float* __restrict__ w1, const float* __restrict__ bb1,
                const float* __restrict__ w2, const float* __restrict__ bb2,
                float* __restrict__ out)
{
    extern __shared__ float smf[];
    float* h2T  = smf + B_H2T;
    float* hidT = smf + B_HID;

    const int tid = threadIdx.x;
    const int t0 = blockIdx.x * NW;

    // ---- LN2 -> h2T[c][n]
    {
        const int n = tid >> 3, q8 = tid & 7;
        const float* yr = g_ybuf + (size_t)(t0 + n) * C + q8 * 12;
        float v[12]; float s = 0.f, ss = 0.f;
        #pragma unroll
        for (int j = 0; j < 12; j++) { float t = yr[j]; v[j] = t; s += t; ss += t * t; }
        s  += __shfl_xor_sync(0xffffffffu, s, 1);  ss += __shfl_xor_sync(0xffffffffu, ss, 1);
        s  += __shfl_xor_sync(0xffffffffu, s, 2);  ss += __shfl_xor_sync(0xffffffffu, ss, 2);
        s  += __shfl_xor_sync(0xffffffffu, s, 4);  ss += __shfl_xor_sync(0xffffffffu, ss, 4);
        float mean = s * (1.f / 96.f);
        float var  = ss * (1.f / 96.f) - mean * mean;
        float rstd = rsqrtf(var + 1e-5f);
        #pragma unroll
        for (int j = 0; j < 12; j++) {
            int c = q8 * 12 + j;
            h2T[c * 68 + n] = (v[j] - mean) * rstd * g2[c] + b2[c];
        }
    }
    __syncthreads();

    // ---- GEMM1 [64x96]@[96x384] + GELU -> hidT[c][row]
    {
        const int rg = tid >> 6, lane64 = tid & 63;
        const int r0 = rg * 8;
        u64t acc[4][6];
        #pragma unroll
        for (int j = 0; j < 6; j++) {
            u64t bj = dup2(bb1[lane64 + 64 * j]);
            #pragma unroll
            for (int p = 0; p < 4; p++) acc[p][j] = bj;
        }
        #pragma unroll 2
        for (int k = 0; k < C; k++) {
            u64t a[4];
            #pragma unroll
            for (int p = 0; p < 4; p++) a[p] = ldsb64(h2T + k * 68 + r0 + 2 * p);
            const float* wr = w1 + k * MLPH + lane64;
            #pragma unroll
            for (int j = 0; j < 6; j++) {
                u64t wd = dup2(__ldg(wr + 64 * j));
                #pragma unroll
                for (int p = 0; p < 4; p++) fma2(acc[p][j], a[p], wd);
            }
        }
        #pragma unroll
        for (int p = 0; p < 4; p++)
            #pragma unroll
            for (int j = 0; j < 6; j++) {
                float2 t = up2(acc[p][j]);
                float gx = 0.5f * t.x * (1.0f + erff(t.x * 0.70710678118654752f));
                float gy = 0.5f * t.y * (1.0f + erff(t.y * 0.70710678118654752f));
                stsb64(hidT + (lane64 + 64 * j) * 68 + r0 + 2 * p, pk2(gx, gy));
            }
    }
    __syncthreads();

    // ---- GEMM2 [64x384]@[384x96], split-K over 2 halves of the block
    {
        const int kh = tid >> 8;            // 0 or 1
        const int t2 = tid & 255;
        const int rg = t2 >> 5, lane = t2 & 31;
        const int r0 = rg * 8;
        u64t acc[4][3];
        #pragma unroll
        for (int j = 0; j < 3; j++) {
            u64t bj = (kh == 0) ? dup2(bb2[lane + 32 * j]) : 0ull;
            #pragma unroll
            for (int p = 0; p < 4; p++) acc[p][j] = bj;
        }
        const int k0 = kh * 192;
        #pragma unroll 2
        for (int kk = 0; kk < 192; kk++) {
            int k = k0 + kk;
            u64t a[4];
            #pragma unroll
            for (int p = 0; p < 4; p++) a[p] = ldsb64(hidT + k * 68 + r0 + 2 * p);
            const float* wr = w2 + k * C + lane;
            #pragma unroll
            for (int j = 0; j < 3; j++) {
                u64t wd = dup2(__ldg(wr + 32 * j));
                #pragma unroll
                for (int p = 0; p < 4; p++) fma2(acc[p][j], a[p], wd);
            }
        }
        float* red = h2T;   // reuse as [64][100] partial buffer
        if (kh == 1) {
            #pragma unroll
            for (int p = 0; p < 4; p++) {
                int r = r0 + 2 * p;
                #pragma unroll
                for (int j = 0; j < 3; j++) {
                    int c = lane + 32 * j;
                    float2 t = up2(acc[p][j]);
                    red[r * 100 + c] = t.x;
                    red[(r + 1) * 100 + c] = t.y;
                }
            }
        }
        __syncthreads();
        if (kh == 0) {
            #pragma unroll
            for (int p = 0; p < 4; p++) {
                int r = r0 + 2 * p;
                size_t b0 = (size_t)(t0 + r) * C;
                size_t b1 = (size_t)(t0 + r + 1) * C;
                #pragma unroll
                for (int j = 0; j < 3; j++) {
                    int c = lane + 32 * j;
                    float2 t = up2(acc[p][j]);
                    out[b0 + c] = g_ybuf[b0 + c] + t.x + red[r * 100 + c];
                    out[b1 + c] = g_ybuf[b1 + c] + t.y + red[(r + 1) * 100 + c];
                }
            }
        }
    }
}

// ---------------------------------------------------------------------------
extern "C" void kernel_launch(void* const* d_in, const int* in_sizes, int n_in,
                              void* d_out, int out_size)
{
    const float* x        = (const float*)d_in[0];
    const float* norm1_g  = (const float*)d_in[1];
    const float* norm1_b  = (const float*)d_in[2];
    const float* qkv_w    = (const float*)d_in[3];
    const float* qkv_b    = (const float*)d_in[4];
    const float* proj_w   = (const float*)d_in[5];
    const float* proj_b   = (const float*)d_in[6];
    const float* bias_tab = (const float*)d_in[7];
    const float* norm2_g  = (const float*)d_in[8];
    const float* norm2_b  = (const float*)d_in[9];
    const float* mlp_w1   = (const float*)d_in[10];
    const float* mlp_b1   = (const float*)d_in[11];
    const float* mlp_w2   = (const float*)d_in[12];
    const float* mlp_b2   = (const float*)d_in[13];
    float* out = (float*)d_out;

    const int SMEM_A = A_TOT * 4;
    const int SMEM_B = B_TOT * 4;

    cudaFuncSetAttribute(win_attn_kernel,
                         cudaFuncAttributeMaxDynamicSharedMemorySize, SMEM_A);
    cudaFuncSetAttribute(mlp_kernel,
                         cudaFuncAttributeMaxDynamicSharedMemorySize, SMEM_B);

    win_attn_kernel<<<NBLK_A, 512, SMEM_A>>>(x, norm1_g, norm1_b,
                                             qkv_w, qkv_b, proj_w, proj_b,
                                             bias_tab);
    mlp_kernel<<<(BATCH * LTOK) / NW, 512, SMEM_B>>>(norm2_g, norm2_b,
                                                     mlp_w1, mlp_b1,
                                                     mlp_w2, mlp_b2, out);
}